// round 15
// baseline (speedup 1.0000x reference)
#include <cuda_runtime.h>
#include <cuda_fp16.h>
#include <mma.h>
#include <stdint.h>
using namespace nvcuda;

#define Bq   64
#define Ec   8978
#define E2c  4489
#define N1   574592      // B*E   = 64*8978
#define N2   287296      // B*E2  = 64*4489
#define NE1  9193472     // N1*16
#define NE2  4596736     // N2*16
#define SLOPE 0.33f
#define NSL  14          // layer-0 slices per graph
#define SLN  642
#define NSB  896         // 64*14 -> 6 blocks/SM, one wave

// ---------------- scratch (device globals; no allocations) ----------------
__device__ float    dT1a[N1], dT2a[N1], dT3a[N1];
__device__ float    dX2[N2 * 32];
__device__ float    dT1v[N2 * 32], dT2v[N2 * 32];
__device__ float    dOutB[N2 * 32];
__device__ __half   dX2h[N2 * 32], dT1h[N2 * 32], dT2h[N2 * 32], dT3h[N2 * 32], dX3h[N2 * 32];
__device__ float    dXfPre[N2];
__device__ double   dAcc[128];
__device__ float    dScale[33], dShift[33];
__device__ float    dH1[Bq * 256], dH2[Bq * 128];

// ---------------- init: H1 bias + dAcc zero (launch 1) ----------------
__global__ void k_init(const float* __restrict__ l1b) {
    int b = blockIdx.x;
    if (b < 64) { dH1[b * 256 + threadIdx.x] = l1b[threadIdx.x]; return; }
    if (threadIdx.x < 128) dAcc[threadIdx.x] = 0.0;
}

// ---------------- layer 0: smem-staged scalar matvec, 2 nodes per thread ----
__global__ void __launch_bounds__(256)
k_mv_scalar_s(const float* __restrict__ v, const float* __restrict__ p,
              float* __restrict__ out, const int* __restrict__ src,
              const float* __restrict__ ew,
              float alpha, float beta, float gamma) {
    __shared__ float vs[Ec];
    int b = blockIdx.x;
    int g = b / NSL, s = b - g * NSL;
    int gbase = g * Ec;
    for (int i = threadIdx.x; i < Ec; i += 256) vs[i] = v[gbase + i];
    __syncthreads();
    int start = s * SLN;
    int end = start + SLN; if (end > Ec) end = Ec;
    for (int base = start + (int)threadIdx.x; base < end; base += 512) {
        int n0 = base;
        int n1 = base + 256;
        bool hv1 = n1 < end;
        int m1 = hv1 ? n1 : n0;
        int gn0 = gbase + n0, gm1 = gbase + m1;
        const int4*   s4a = (const int4*)(src + (size_t)gn0 * 16);
        const float4* w4a = (const float4*)(ew + (size_t)gn0 * 16);
        const int4*   s4b = (const int4*)(src + (size_t)gm1 * 16);
        const float4* w4b = (const float4*)(ew + (size_t)gm1 * 16);
        // issue all 8 index/weight vector loads up front (MLP)
        int4 ssa0 = __ldg(&s4a[0]), ssa1 = __ldg(&s4a[1]);
        int4 ssa2 = __ldg(&s4a[2]), ssa3 = __ldg(&s4a[3]);
        int4 ssb0 = __ldg(&s4b[0]), ssb1 = __ldg(&s4b[1]);
        int4 ssb2 = __ldg(&s4b[2]), ssb3 = __ldg(&s4b[3]);
        float4 wwa0 = __ldg(&w4a[0]), wwa1 = __ldg(&w4a[1]);
        float4 wwa2 = __ldg(&w4a[2]), wwa3 = __ldg(&w4a[3]);
        float4 wwb0 = __ldg(&w4b[0]), wwb1 = __ldg(&w4b[1]);
        float4 wwb2 = __ldg(&w4b[2]), wwb3 = __ldg(&w4b[3]);
        float a0 = 0.f, a1 = 0.f, b0 = 0.f, b1 = 0.f;
        // interleaved LDS chains for the two nodes
        a0 += wwa0.x * vs[ssa0.x - gbase]; b0 += wwb0.x * vs[ssb0.x - gbase];
        a1 += wwa0.y * vs[ssa0.y - gbase]; b1 += wwb0.y * vs[ssb0.y - gbase];
        a0 += wwa0.z * vs[ssa0.z - gbase]; b0 += wwb0.z * vs[ssb0.z - gbase];
        a1 += wwa0.w * vs[ssa0.w - gbase]; b1 += wwb0.w * vs[ssb0.w - gbase];
        a0 += wwa1.x * vs[ssa1.x - gbase]; b0 += wwb1.x * vs[ssb1.x - gbase];
        a1 += wwa1.y * vs[ssa1.y - gbase]; b1 += wwb1.y * vs[ssb1.y - gbase];
        a0 += wwa1.z * vs[ssa1.z - gbase]; b0 += wwb1.z * vs[ssb1.z - gbase];
        a1 += wwa1.w * vs[ssa1.w - gbase]; b1 += wwb1.w * vs[ssb1.w - gbase];
        a0 += wwa2.x * vs[ssa2.x - gbase]; b0 += wwb2.x * vs[ssb2.x - gbase];
        a1 += wwa2.y * vs[ssa2.y - gbase]; b1 += wwb2.y * vs[ssb2.y - gbase];
        a0 += wwa2.z * vs[ssa2.z - gbase]; b0 += wwb2.z * vs[ssb2.z - gbase];
        a1 += wwa2.w * vs[ssa2.w - gbase]; b1 += wwb2.w * vs[ssb2.w - gbase];
        a0 += wwa3.x * vs[ssa3.x - gbase]; b0 += wwb3.x * vs[ssb3.x - gbase];
        a1 += wwa3.y * vs[ssa3.y - gbase]; b1 += wwb3.y * vs[ssb3.y - gbase];
        a0 += wwa3.z * vs[ssa3.z - gbase]; b0 += wwb3.z * vs[ssb3.z - gbase];
        a1 += wwa3.w * vs[ssa3.w - gbase]; b1 += wwb3.w * vs[ssb3.w - gbase];
        out[gn0] = (alpha * vs[n0] + beta * p[gn0] - (a0 + a1)) * gamma;
        if (hv1)
            out[gm1] = (alpha * vs[m1] + beta * p[gm1] - (b0 + b1)) * gamma;
    }
}

// 4 means + 10 second moments of (x, T1, T2, T3) -> dAcc[0..14)
__global__ void k_stats0(const float* __restrict__ x) {
    float loc[14];
#pragma unroll
    for (int i = 0; i < 14; i++) loc[i] = 0.f;
    const float4* X = (const float4*)x;
    const float4* A = (const float4*)dT1a;
    const float4* B = (const float4*)dT2a;
    const float4* C = (const float4*)dT3a;
    int stride = gridDim.x * blockDim.x;
    for (int i = blockIdx.x * blockDim.x + threadIdx.x; i < N1 / 4; i += stride) {
        float4 a = X[i], b = A[i], c = B[i], d = C[i];
        float t0[4] = {a.x, a.y, a.z, a.w};
        float t1[4] = {b.x, b.y, b.z, b.w};
        float t2[4] = {c.x, c.y, c.z, c.w};
        float t3[4] = {d.x, d.y, d.z, d.w};
#pragma unroll
        for (int u = 0; u < 4; u++) {
            loc[0] += t0[u]; loc[1] += t1[u]; loc[2] += t2[u]; loc[3] += t3[u];
            loc[4]  += t0[u] * t0[u]; loc[5]  += t0[u] * t1[u];
            loc[6]  += t0[u] * t2[u]; loc[7]  += t0[u] * t3[u];
            loc[8]  += t1[u] * t1[u]; loc[9]  += t1[u] * t2[u];
            loc[10] += t1[u] * t3[u]; loc[11] += t2[u] * t2[u];
            loc[12] += t2[u] * t3[u]; loc[13] += t3[u] * t3[u];
        }
    }
#pragma unroll
    for (int o = 16; o > 0; o >>= 1)
#pragma unroll
        for (int i = 0; i < 14; i++)
            loc[i] += __shfl_down_sync(0xffffffffu, loc[i], o);
    __shared__ double sh[8][14];
    int w = threadIdx.x >> 5, l = threadIdx.x & 31;
    if (l == 0)
        for (int i = 0; i < 14; i++) sh[w][i] = (double)loc[i];
    __syncthreads();
    if (threadIdx.x == 0) {
        for (int i = 0; i < 14; i++) {
            double s = 0;
            for (int w2 = 0; w2 < 8; w2++) s += sh[w2][i];
            atomicAdd(&dAcc[i], s);
        }
    }
}

__global__ void k_prep0(const float* __restrict__ W0,
                        const float* __restrict__ g0, const float* __restrict__ be0) {
    int c = threadIdx.x;
    if (c >= 32) return;
    double m[4], w[4];
    for (int k = 0; k < 4; k++) { m[k] = dAcc[k] / (double)N1; w[k] = W0[k * 32 + c]; }
    double mean = 0.0;
    for (int k = 0; k < 4; k++) mean += m[k] * w[k];
    const int idx[4][4] = {{4,5,6,7},{5,8,9,10},{6,9,11,12},{7,10,12,13}};
    double var = 0;
    for (int k = 0; k < 4; k++)
        for (int l = 0; l < 4; l++)
            var += w[k] * w[l] * (dAcc[idx[k][l]] / (double)N1 - m[k] * m[l]);
    double sc = (double)g0[c] / sqrt(var + 1e-5);
    dScale[c] = (float)sc;
    dShift[c] = (float)((double)be0[c] - mean * sc);
}

// fused: project T->32ch, BN affine, LeakyReLU, Graclus pair-max pool
__global__ void k_pool(const float* __restrict__ x, const float* __restrict__ W0) {
    int t = blockIdx.x * blockDim.x + threadIdx.x;
    int p = t >> 5;
    if (p >= N2) return;
    int c = t & 31;
    float w0 = W0[c], w1 = W0[32 + c], w2 = W0[64 + c], w3 = W0[96 + c];
    float sc = dScale[c], sh = dShift[c];
    int n0 = 2 * p, n1 = 2 * p + 1;
    float o0 = x[n0] * w0 + dT1a[n0] * w1 + dT2a[n0] * w2 + dT3a[n0] * w3;
    float o1 = x[n1] * w0 + dT1a[n1] * w1 + dT2a[n1] * w2 + dT3a[n1] * w3;
    o0 = o0 * sc + sh; o0 = o0 > 0.f ? o0 : SLOPE * o0;
    o1 = o1 * sc + sh; o1 = o1 > 0.f ? o1 : SLOPE * o1;
    float r = fmaxf(o0, o1);
    dX2[p * 32 + c]  = r;
    dX2h[p * 32 + c] = __float2half(r);
}

// ---------------- layers 1/2: 32-dim matvec + Laguerre combine -------------
// FOUR nodes per warp: 8 lanes per node, lane owns 4 channels (uint2 gather).
__global__ void k_mv_vec(const float* __restrict__ v, const __half* __restrict__ vh,
                         const float* __restrict__ p,
                         float* __restrict__ out, __half* __restrict__ outh,
                         const int* __restrict__ src, const float* __restrict__ ew,
                         float alpha, float beta, float gamma, int write_f32) {
    int t = blockIdx.x * blockDim.x + threadIdx.x;
    int warp = t >> 5;
    int lane = t & 31;
    int qtr = lane >> 3;
    int hl  = lane & 7;
    int node = warp * 4 + qtr;
    int base = node * 16;
    int   sl0 = src[base + hl];
    int   sl1 = src[base + 8 + hl];
    float wl0 = ew[base + hl];
    float wl1 = ew[base + 8 + hl];
    int qb = qtr << 3;
    float a0 = 0.f, a1 = 0.f, a2 = 0.f, a3 = 0.f;
#pragma unroll
    for (int e = 0; e < 8; e++) {
        int   s  = __shfl_sync(0xffffffffu, sl0, qb + e);
        float wt = __shfl_sync(0xffffffffu, wl0, qb + e);
        uint2 d = __ldg((const uint2*)(vh + (size_t)s * 32) + hl);
        float2 f0 = __half22float2(*(__half2*)&d.x);
        float2 f1 = __half22float2(*(__half2*)&d.y);
        a0 += wt * f0.x; a1 += wt * f0.y; a2 += wt * f1.x; a3 += wt * f1.y;
    }
#pragma unroll
    for (int e = 0; e < 8; e++) {
        int   s  = __shfl_sync(0xffffffffu, sl1, qb + e);
        float wt = __shfl_sync(0xffffffffu, wl1, qb + e);
        uint2 d = __ldg((const uint2*)(vh + (size_t)s * 32) + hl);
        float2 f0 = __half22float2(*(__half2*)&d.x);
        float2 f1 = __half22float2(*(__half2*)&d.y);
        a0 += wt * f0.x; a1 += wt * f0.y; a2 += wt * f1.x; a3 += wt * f1.y;
    }
    size_t o = (size_t)node * 32 + 4 * hl;
    float4 vv = *(const float4*)(v + o);
    float4 pp = *(const float4*)(p + o);
    float r0 = (alpha * vv.x + beta * pp.x - a0) * gamma;
    float r1 = (alpha * vv.y + beta * pp.y - a1) * gamma;
    float r2 = (alpha * vv.z + beta * pp.z - a2) * gamma;
    float r3 = (alpha * vv.w + beta * pp.w - a3) * gamma;
    if (write_f32) *(float4*)(out + o) = make_float4(r0, r1, r2, r3);
    uint2 ho;
    *(__half2*)&ho.x = __floats2half2_rn(r0, r1);
    *(__half2*)&ho.y = __floats2half2_rn(r2, r3);
    *(uint2*)(outh + o) = ho;
}

// out = [A0|A1|A2|A3](fp16) @ W(128x32) split-precision (Wh+Wl), tensor cores.
__global__ void __launch_bounds__(256)
k_outgemm_mma(const __half* __restrict__ A0, const __half* __restrict__ A1,
              const __half* __restrict__ A2, const __half* __restrict__ A3,
              const float* __restrict__ W, float* __restrict__ out) {
    __shared__ __half Wh[2][128][40];
    __shared__ float ssum[32], ssq[32];
    int t = threadIdx.x;
    int nb = blockIdx.x * 128;
    if (t < 32) { ssum[t] = 0.f; ssq[t] = 0.f; }
    for (int i = t; i < 4096; i += 256) {
        int k = i >> 5, c = i & 31;
        float w = W[i];
        __half h = __float2half(w);
        Wh[0][k][c] = h;
        Wh[1][k][c] = __float2half(w - __half2float(h));
    }
    __syncthreads();
    int w = t >> 5;
    const __half* Aks[4] = {A0, A1, A2, A3};
    wmma::fragment<wmma::accumulator, 16, 16, 16, float> c0, c1;
    wmma::fill_fragment(c0, 0.f);
    wmma::fill_fragment(c1, 0.f);
#pragma unroll
    for (int k0 = 0; k0 < 8; k0++) {
        const __half* Ak = Aks[k0 >> 1];
        wmma::fragment<wmma::matrix_a, 16, 16, 16, __half, wmma::row_major> a;
        wmma::load_matrix_sync(a, Ak + (size_t)(nb + w * 16) * 32 + (k0 & 1) * 16, 32);
        wmma::fragment<wmma::matrix_b, 16, 16, 16, __half, wmma::row_major> b;
        wmma::load_matrix_sync(b, &Wh[0][k0 * 16][0], 40);
        wmma::mma_sync(c0, a, b, c0);
        wmma::load_matrix_sync(b, &Wh[1][k0 * 16][0], 40);
        wmma::mma_sync(c0, a, b, c0);
        wmma::load_matrix_sync(b, &Wh[0][k0 * 16][16], 40);
        wmma::mma_sync(c1, a, b, c1);
        wmma::load_matrix_sync(b, &Wh[1][k0 * 16][16], 40);
        wmma::mma_sync(c1, a, b, c1);
    }
    __syncthreads();
    float* Cs = (float*)&Wh[0][0][0];     // [128][36]
    wmma::store_matrix_sync(&Cs[(w * 16) * 36], c0, 36, wmma::mem_row_major);
    wmma::store_matrix_sync(&Cs[(w * 16) * 36 + 16], c1, 36, wmma::mem_row_major);
    __syncthreads();
    int c = t & 31, r0 = (t >> 5) * 16;
    float s = 0.f, q = 0.f;
    for (int r = r0; r < r0 + 16; r++) {
        int g = nb + r;
        if (g < N2) {
            float vv = Cs[r * 36 + c];
            s += vv; q += vv * vv;
            out[(size_t)g * 32 + c] = vv;
        }
    }
    atomicAdd(&ssum[c], s);
    atomicAdd(&ssq[c], q);
    __syncthreads();
    if (t < 32) {
        atomicAdd(&dAcc[16 + t], (double)ssum[t]);
        atomicAdd(&dAcc[48 + t], (double)ssq[t]);
    }
}

// single block: layer-1 BN scale/shift
__global__ void k_prep32(const float* __restrict__ g, const float* __restrict__ be) {
    int c = threadIdx.x;
    if (c >= 32) return;
    double mean = dAcc[16 + c] / (double)N2;
    double var  = dAcc[48 + c] / (double)N2 - mean * mean;
    double sc = (double)g[c] / sqrt(var + 1e-5);
    dScale[c] = (float)sc;
    dShift[c] = (float)((double)be[c] - mean * sc);
}

// BN affine + LeakyReLU, in place; writes fp16 copy. float4 vectorized.
__global__ void k_apply32(float* __restrict__ a, __half* __restrict__ ah) {
    int i = blockIdx.x * blockDim.x + threadIdx.x;   // over N2*8
    float4 v = ((const float4*)a)[i];
    int c = (i & 7) * 4;
    float s0 = dScale[c],     h0 = dShift[c];
    float s1 = dScale[c + 1], h1 = dShift[c + 1];
    float s2 = dScale[c + 2], h2 = dShift[c + 2];
    float s3 = dScale[c + 3], h3 = dShift[c + 3];
    v.x = v.x * s0 + h0; v.x = v.x > 0.f ? v.x : SLOPE * v.x;
    v.y = v.y * s1 + h1; v.y = v.y > 0.f ? v.y : SLOPE * v.y;
    v.z = v.z * s2 + h2; v.z = v.z > 0.f ? v.z : SLOPE * v.z;
    v.w = v.w * s3 + h3; v.w = v.w > 0.f ? v.w : SLOPE * v.w;
    ((float4*)a)[i] = v;
    ((__half2*)ah)[i * 2]     = __floats2half2_rn(v.x, v.y);
    ((__half2*)ah)[i * 2 + 1] = __floats2half2_rn(v.z, v.w);
}

// layer2 final, 4 nodes/warp: gather T2 (uint2), form T3 quad, dot with W2
__global__ void k_mv_out2(const float* __restrict__ v, const __half* __restrict__ vh,
                          const float* __restrict__ p, const float* __restrict__ x3,
                          const int* __restrict__ src, const float* __restrict__ ew,
                          const float* __restrict__ W2) {
    int t = blockIdx.x * blockDim.x + threadIdx.x;
    int warp = t >> 5;
    int lane = t & 31;
    int qtr = lane >> 3;
    int hl  = lane & 7;
    int node = warp * 4 + qtr;
    int base = node * 16;
    int   sl0 = src[base + hl];
    int   sl1 = src[base + 8 + hl];
    float wl0 = ew[base + hl];
    float wl1 = ew[base + 8 + hl];
    int qb = qtr << 3;
    float a0 = 0.f, a1 = 0.f, a2 = 0.f, a3 = 0.f;
#pragma unroll
    for (int e = 0; e < 8; e++) {
        int   s  = __shfl_sync(0xffffffffu, sl0, qb + e);
        float wt = __shfl_sync(0xffffffffu, wl0, qb + e);
        uint2 d = __ldg((const uint2*)(vh + (size_t)s * 32) + hl);
        float2 f0 = __half22float2(*(__half2*)&d.x);
        float2 f1 = __half22float2(*(__half2*)&d.y);
        a0 += wt * f0.x; a1 += wt * f0.y; a2 += wt * f1.x; a3 += wt * f1.y;
    }
#pragma unroll
    for (int e = 0; e < 8; e++) {
        int   s  = __shfl_sync(0xffffffffu, sl1, qb + e);
        float wt = __shfl_sync(0xffffffffu, wl1, qb + e);
        uint2 d = __ldg((const uint2*)(vh + (size_t)s * 32) + hl);
        float2 f0 = __half22float2(*(__half2*)&d.x);
        float2 f1 = __half22float2(*(__half2*)&d.y);
        a0 += wt * f0.x; a1 += wt * f0.y; a2 += wt * f1.x; a3 += wt * f1.y;
    }
    size_t o = (size_t)node * 32 + 4 * hl;
    float4 vv = *(const float4*)(v + o);     // T2
    float4 pp = *(const float4*)(p + o);     // T1
    float4 xx = *(const float4*)(x3 + o);    // layer-2 input
    int jc = 4 * hl;
    float4 u0 = *(const float4*)(W2 + jc);
    float4 u1 = *(const float4*)(W2 + 32 + jc);
    float4 u2 = *(const float4*)(W2 + 64 + jc);
    float4 u3 = *(const float4*)(W2 + 96 + jc);
    const float c3 = 1.f / 3.f;
    float t30 = (5.f * vv.x - 2.f * pp.x - a0) * c3;
    float t31 = (5.f * vv.y - 2.f * pp.y - a1) * c3;
    float t32 = (5.f * vv.z - 2.f * pp.z - a2) * c3;
    float t33 = (5.f * vv.w - 2.f * pp.w - a3) * c3;
    float val = xx.x * u0.x + xx.y * u0.y + xx.z * u0.z + xx.w * u0.w +
                pp.x * u1.x + pp.y * u1.y + pp.z * u1.z + pp.w * u1.w +
                vv.x * u2.x + vv.y * u2.y + vv.z * u2.z + vv.w * u2.w +
                t30 * u3.x + t31 * u3.y + t32 * u3.z + t33 * u3.w;
#pragma unroll
    for (int off = 4; off > 0; off >>= 1)
        val += __shfl_down_sync(0xffffffffu, val, off, 8);
    __shared__ float sh_s[32], sh_q[32];
    int wslot = (threadIdx.x >> 5) * 4 + qtr;
    if (hl == 0) {                   // b2 dropped: BN-invariant
        dXfPre[node] = val;
        sh_s[wslot] = val;
        sh_q[wslot] = val * val;
    }
    __syncthreads();
    if (threadIdx.x == 0) {
        float s = 0, q = 0;
        for (int i = 0; i < 32; i++) { s += sh_s[i]; q += sh_q[i]; }
        atomicAdd(&dAcc[96], (double)s);
        atomicAdd(&dAcc[97], (double)q);
    }
}

// ---------------- MLP head ----------------
__global__ void k_lin1(const float* __restrict__ W,
                       const float* __restrict__ g2, const float* __restrict__ be2) {
    __shared__ float sm[16 * 128];
    __shared__ float sSc, sSh;
    int c = threadIdx.x;
    if (c == 0) {
        double mean = dAcc[96] / (double)N2;
        double var  = dAcc[97] / (double)N2 - mean * mean;
        double sc = (double)g2[0] / sqrt(var + 1e-5);
        sSc = (float)sc;
        sSh = (float)((double)be2[0] - mean * sc);
    }
    __syncthreads();
    int jbase = blockIdx.x * 128;
    int rbase = blockIdx.y * 16;
    for (int i = c; i < 16 * 128; i += 256) {
        int r = i >> 7, j = i & 127, gj = jbase + j;
        float v = 0.f;
        if (gj < E2c) {
            v = dXfPre[(rbase + r) * E2c + gj] * sSc + sSh;
            v = v > 0.f ? v : SLOPE * v;
        }
        sm[i] = v;
    }
    __syncthreads();
    int jlim = E2c - jbase; if (jlim > 128) jlim = 128;
    float acc[16];
#pragma unroll
    for (int r = 0; r < 16; r++) acc[r] = 0.f;
    for (int j = 0; j < jlim; j++) {
        float w = __ldg(&W[(jbase + j) * 256 + c]);
#pragma unroll
        for (int r = 0; r < 16; r++) acc[r] += sm[r * 128 + j] * w;
    }
#pragma unroll
    for (int r = 0; r < 16; r++)
        atomicAdd(&dH1[(rbase + r) * 256 + c], acc[r]);
}

__global__ void k_bnrelu(float* __restrict__ H, const float* __restrict__ g,
                         const float* __restrict__ be, int C) {
    int c = threadIdx.x;
    if (c >= C) return;
    float s = 0, q = 0;
    for (int r = 0; r < Bq; r++) { float v = H[r * C + c]; s += v; q += v * v; }
    float mean = s / (float)Bq, var = q / (float)Bq - mean * mean;
    float sc = g[c] * rsqrtf(var + 1e-5f);
    float sh = be[c] - mean * sc;
    for (int r = 0; r < Bq; r++) {
        float v = H[r * C + c] * sc + sh;
        H[r * C + c] = fmaxf(v, 0.f);
    }
}

__global__ void k_lin2(const float* __restrict__ H1, const float* __restrict__ W,
                       const float* __restrict__ bias, float* __restrict__ H2) {
    __shared__ float row[256];
    int b = blockIdx.x, t = threadIdx.x;
    row[t] = H1[b * 256 + t];
    __syncthreads();
    if (t < 128) {
        float acc = bias[t];
        for (int j = 0; j < 256; j++)
            acc += row[j] * W[j * 128 + t];
        H2[b * 128 + t] = acc;
    }
}

__global__ void k_lin3(const float* __restrict__ H2, const float* __restrict__ W,
                       const float* __restrict__ bias, float* __restrict__ out) {
    int b = blockIdx.x, t = threadIdx.x;
    float p = H2[b * 128 + t] * W[t];
#pragma unroll
    for (int o = 16; o > 0; o >>= 1)
        p += __shfl_down_sync(0xffffffffu, p, o);
    __shared__ float sh[4];
    if ((t & 31) == 0) sh[t >> 5] = p;
    __syncthreads();
    if (t == 0) out[b] = sh[0] + sh[1] + sh[2] + sh[3] + bias[0];
}

// ---------------- launch ----------------
extern "C" void kernel_launch(void* const* d_in, const int* in_sizes, int n_in,
                              void* d_out, int out_size) {
    const float* x_s  = (const float*)d_in[0];
    const int*   ei1  = (const int*)d_in[1];
    const float* ew1  = (const float*)d_in[2];
    const int*   ei2  = (const int*)d_in[3];
    const float* ew2  = (const float*)d_in[4];
    const float* W0   = (const float*)d_in[5];
    const float* g0   = (const float*)d_in[7];
    const float* be0  = (const float*)d_in[8];
    const float* W1   = (const float*)d_in[9];
    const float* g1   = (const float*)d_in[11];
    const float* be1  = (const float*)d_in[12];
    const float* W2   = (const float*)d_in[13];
    const float* g2   = (const float*)d_in[15];
    const float* be2  = (const float*)d_in[16];
    const float* l1W  = (const float*)d_in[17];
    const float* l1b  = (const float*)d_in[18];
    const float* bn1g = (const float*)d_in[19];
    const float* bn1b = (const float*)d_in[20];
    const float* l2W  = (const float*)d_in[21];
    const float* l2b  = (const float*)d_in[22];
    const float* bn2g = (const float*)d_in[23];
    const float* bn2b = (const float*)d_in[24];
    const float* l3W  = (const float*)d_in[25];
    const float* l3b  = (const float*)d_in[26];

    const int* src1 = ei1;
    const int* src2 = ei2;

    float *pT1a, *pT2a, *pT3a, *pX2, *pT1, *pT2, *pOut, *pH1, *pH2;
    __half *pX2h, *pT1h, *pT2h, *pT3h, *pX3h;
    cudaGetSymbolAddress((void**)&pT1a, dT1a);
    cudaGetSymbolAddress((void**)&pT2a, dT2a);
    cudaGetSymbolAddress((void**)&pT3a, dT3a);
    cudaGetSymbolAddress((void**)&pX2, dX2);
    cudaGetSymbolAddress((void**)&pT1, dT1v);
    cudaGetSymbolAddress((void**)&pT2, dT2v);
    cudaGetSymbolAddress((void**)&pOut, dOutB);
    cudaGetSymbolAddress((void**)&pH1, dH1);
    cudaGetSymbolAddress((void**)&pH2, dH2);
    cudaGetSymbolAddress((void**)&pX2h, dX2h);
    cudaGetSymbolAddress((void**)&pT1h, dT1h);
    cudaGetSymbolAddress((void**)&pT2h, dT2h);
    cudaGetSymbolAddress((void**)&pT3h, dT3h);
    cudaGetSymbolAddress((void**)&pX3h, dX3h);

    const int NBV  = (N2 * 32) / 256;   // 35912
    const int NBV4 = (N2 * 8) / 256;    // 8978 (4-nodes-per-warp kernels)

    // ---- init (launch 1) ----
    k_init<<<65, 256>>>(l1b);

    // ---- layer 0 (2 nodes/thread ILP) ----
    k_mv_scalar_s<<<NSB, 256>>>(x_s, x_s, pT1a, src1, ew1, 1.f, 0.f, 1.f);
    k_mv_scalar_s<<<NSB, 256>>>(pT1a, x_s, pT2a, src1, ew1, 3.f, -1.f, 0.5f);
    k_mv_scalar_s<<<NSB, 256>>>(pT2a, pT1a, pT3a, src1, ew1, 5.f, -2.f, 1.f / 3.f);
    k_stats0<<<562, 256>>>(x_s);
    k_prep0<<<1, 32>>>(W0, g0, be0);
    k_pool<<<NBV, 256>>>(x_s, W0);

    // ---- layer 1 (32ch Laguerre conv, 4 nodes/warp) ----
    k_mv_vec<<<NBV4, 256>>>(pX2, pX2h, pX2, pT1, pT1h, src2, ew2, 1.f, 0.f, 1.f, 1);
    k_mv_vec<<<NBV4, 256>>>(pT1, pT1h, pX2, pT2, pT2h, src2, ew2, 3.f, -1.f, 0.5f, 1);
    k_mv_vec<<<NBV4, 256>>>(pT2, pT2h, pT1, pT2, pT3h, src2, ew2, 5.f, -2.f, 1.f / 3.f, 0);
    k_outgemm_mma<<<(N2 + 127) / 128, 256>>>(pX2h, pT1h, pT2h, pT3h, W1, pOut);
    k_prep32<<<1, 32>>>(g1, be1);
    k_apply32<<<(N2 * 8) / 256, 256>>>(pOut, pX3h);    // in-place -> x3 (+fp16)

    // ---- layer 2 (32ch -> 1ch Laguerre conv, output fused, 4 nodes/warp) ----
    k_mv_vec<<<NBV4, 256>>>(pOut, pX3h, pOut, pT1, pT1h, src2, ew2, 1.f, 0.f, 1.f, 1);
    k_mv_vec<<<NBV4, 256>>>(pT1, pT1h, pOut, pT2, pT2h, src2, ew2, 3.f, -1.f, 0.5f, 1);
    k_mv_out2<<<NBV4, 256>>>(pT2, pT2h, pT1, pOut, src2, ew2, W2);

    // ---- MLP head (layer-2 BN fused into lin1) ----
    k_lin1<<<dim3(36, 4), 256>>>(l1W, g2, be2);
    k_bnrelu<<<1, 256>>>(pH1, bn1g, bn1b, 256);
    k_lin2<<<Bq, 256>>>(pH1, l2W, l2b, pH2);
    k_bnrelu<<<1, 128>>>(pH2, bn2g, bn2b, 128);
    k_lin3<<<Bq, 128>>>(pH2, l3W, l3b, (float*)d_out);
}